// round 13
// baseline (speedup 1.0000x reference)
#include <cuda_runtime.h>
#include <cstdint>

// Problem constants
#define NB   8
#define CIN  16
#define LL   1024
#define DDIM 7
#define SZ   112     // CIN*DDIM
#define HH   16
#define DP   8       // padded head dim
#define SPLIT 8
#define KCH  (LL / SPLIT)   // 128 keys per block

// Scratch: Q/K/V in [n][h][l][8] (4MB each), partials [ks][bh][l][8]
__device__ float g_q[NB * HH * LL * DP];   // q pre-scaled by log2(e)/32
__device__ float g_k[NB * HH * LL * DP];
__device__ float g_v[NB * HH * LL * DP];
__device__ float g_part[SPLIT * NB * HH * LL * DP];

// ---------------- f32x2 packed helpers ----------------
using u64 = unsigned long long;

__device__ __forceinline__ u64 pk2(float lo, float hi) {
    u64 r; asm("mov.b64 %0,{%1,%2};" : "=l"(r) : "f"(lo), "f"(hi)); return r;
}
__device__ __forceinline__ u64 dup2(float v) {
    u64 r; asm("mov.b64 %0,{%1,%1};" : "=l"(r) : "f"(v)); return r;
}
__device__ __forceinline__ void up2(u64 v, float& lo, float& hi) {
    asm("mov.b64 {%0,%1},%2;" : "=f"(lo), "=f"(hi) : "l"(v));
}
__device__ __forceinline__ u64 fma2(u64 a, u64 b, u64 c) {
    u64 d; asm("fma.rn.f32x2 %0,%1,%2,%3;" : "=l"(d) : "l"(a), "l"(b), "l"(c)); return d;
}
__device__ __forceinline__ u64 mul2(u64 a, u64 b) {
    u64 d; asm("mul.rn.f32x2 %0,%1,%2;" : "=l"(d) : "l"(a), "l"(b)); return d;
}
__device__ __forceinline__ u64 add2(u64 a, u64 b) {
    u64 d; asm("add.rn.f32x2 %0,%1,%2;" : "=l"(d) : "l"(a), "l"(b)); return d;
}
__device__ __forceinline__ float ex2f(float a) {
    float d; asm("ex2.approx.f32 %0,%1;" : "=f"(d) : "f"(a)); return d;
}
__device__ __forceinline__ unsigned tf32cvt(float v) {
    unsigned r; asm("cvt.rna.tf32.f32 %0,%1;" : "=r"(r) : "f"(v)); return r;
}

// ---------------- Kernel 1: QKV projection via tf32 mma.sync ----------------
// grid (128, 3): bx -> (n, l-tile of 64), by -> Wq/Wk/Wv. 256 threads = 8 warps.
// Warp w: row-tile (w&3)*16, col-half (w>>2)*56 (7 n-tiles of 8 cols).
// smem: xs[f][l] stride 72 (tf32-converted x, A frags conflict-free:
// bank=8*tig+gid), ws[c][f] stride 116 (tf32 W, B frags conflict-free:
// bank=20*gid+tig). 84KB -> 2 blocks/SM.
#define SXT 72
#define SWS 116
#define GEMM_SMEM ((SZ * SXT + SZ * SWS) * 4)

__global__ void __launch_bounds__(256, 2)
qkv_gemm(const float* __restrict__ x,
         const float* __restrict__ Wq, const float* __restrict__ bq,
         const float* __restrict__ Wk, const float* __restrict__ bk,
         const float* __restrict__ Wv, const float* __restrict__ bv)
{
    extern __shared__ unsigned smu[];
    unsigned* xs = smu;              // [112 f][72 l]  tf32 bits
    unsigned* ws = smu + SZ * SXT;   // [112 c][116 f] tf32 bits

    const int tid = threadIdx.x;
    const int m = blockIdx.y;
    const float* W = (m == 0) ? Wq : ((m == 1) ? Wk : Wv);
    const float* b = (m == 0) ? bq : ((m == 1) ? bk : bv);
    float* og = (m == 0) ? g_q : ((m == 1) ? g_k : g_v);

    const int n  = blockIdx.x >> 4;          // 16 l-tiles per n
    const int l0 = (blockIdx.x & 15) << 6;

    // W -> ws[c][f] (tf32)
    for (int i = tid; i < SZ * SZ; i += 256)
        ws[(i / SZ) * SWS + (i % SZ)] = tf32cvt(W[i]);

    // x [c][l][dd] -> xs[f=c*7+dd][l] (tf32)
    const float* xb = x + ((size_t)n * CIN * LL + l0) * DDIM;
    for (int i = tid; i < CIN * 64 * DDIM; i += 256) {
        int c = i / (64 * DDIM);
        int r = i - c * (64 * DDIM);
        float v = xb[(size_t)c * LL * DDIM + r];
        int l = r / DDIM;
        int dd = r - l * DDIM;
        xs[(c * DDIM + dd) * SXT + l] = tf32cvt(v);
    }
    __syncthreads();

    const int wid  = tid >> 5;
    const int lane = tid & 31;
    const int gid  = lane >> 2;      // 0..7
    const int tig  = lane & 3;       // 0..3
    const int rt   = (wid & 3) * 16; // row tile within l-tile
    const int ch   = wid >> 2;       // col half
    const int cb   = ch * 56;        // base col (head ch*8)

    float c0[7], c1[7], c2[7], c3[7];
#pragma unroll
    for (int nt = 0; nt < 7; ++nt) { c0[nt] = 0.f; c1[nt] = 0.f; c2[nt] = 0.f; c3[nt] = 0.f; }

#pragma unroll
    for (int k = 0; k < 14; ++k) {
        const int f0 = k * 8;
        // A frags: A[r][kk] = xs[(f0+kk)*SXT + l0row]; row = rt+gid(+8), kk = tig(+4)
        unsigned a0 = xs[(f0 + tig) * SXT + rt + gid];
        unsigned a1 = xs[(f0 + tig) * SXT + rt + gid + 8];
        unsigned a2 = xs[(f0 + tig + 4) * SXT + rt + gid];
        unsigned a3 = xs[(f0 + tig + 4) * SXT + rt + gid + 8];
#pragma unroll
        for (int nt = 0; nt < 7; ++nt) {
            const int col = cb + nt * 8 + gid;
            unsigned b0 = ws[col * SWS + f0 + tig];
            unsigned b1 = ws[col * SWS + f0 + tig + 4];
            asm volatile(
                "mma.sync.aligned.m16n8k8.row.col.f32.tf32.tf32.f32 "
                "{%0,%1,%2,%3}, {%4,%5,%6,%7}, {%8,%9}, {%0,%1,%2,%3};"
                : "+f"(c0[nt]), "+f"(c1[nt]), "+f"(c2[nt]), "+f"(c3[nt])
                : "r"(a0), "r"(a1), "r"(a2), "r"(a3), "r"(b0), "r"(b1));
        }
    }

    // Epilogue: add bias, (Q only) scale by log2(e)/32, scatter to [n][h][l][8].
    const float SC = (m == 0) ? 0.04508422002778011f : 1.0f;
    const int rowA = l0 + rt + gid;
    const int rowB = rowA + 8;
#pragma unroll
    for (int nt = 0; nt < 7; ++nt) {
        const int colA = cb + nt * 8 + 2 * tig;
        const int colB = colA + 1;
        const float bA = __ldg(&b[colA]);
        const float bB = __ldg(&b[colB]);
        const int hA = colA / 7, dA = colA - hA * 7;
        const int hB = colB / 7, dB = colB - hB * 7;
        og[(((size_t)n * HH + hA) * LL + rowA) * DP + dA] = (c0[nt] + bA) * SC;
        og[(((size_t)n * HH + hB) * LL + rowA) * DP + dB] = (c1[nt] + bB) * SC;
        og[(((size_t)n * HH + hA) * LL + rowB) * DP + dA] = (c2[nt] + bA) * SC;
        og[(((size_t)n * HH + hB) * LL + rowB) * DP + dB] = (c3[nt] + bB) * SC;
    }
}

// ---------------- Kernel 2: key-split attention partials (R10 exact) ----------------
__global__ void __launch_bounds__(256, 2)
attn_kernel()
{
    __shared__ u64 kd[KCH * 8];
    __shared__ u64 vd[KCH * 8];

    const int tid = threadIdx.x;
    const int bh  = blockIdx.x >> 3;
    const int ks  = blockIdx.x & 7;
    const int kbase = ks * KCH;

    if (tid < KCH) {
        const float4* kp = (const float4*)(g_k + ((size_t)bh * LL + kbase + tid) * DP);
        float4 a = kp[0], c = kp[1];
        u64* o = kd + tid * 8;
        o[0] = dup2(a.x); o[1] = dup2(a.y); o[2] = dup2(a.z); o[3] = dup2(a.w);
        o[4] = dup2(c.x); o[5] = dup2(c.y); o[6] = dup2(c.z); o[7] = 0ull;
    } else {
        int t = tid - KCH;
        const float4* vp = (const float4*)(g_v + ((size_t)bh * LL + kbase + t) * DP);
        float4 a = vp[0], c = vp[1];
        u64* o = vd + t * 8;
        o[0] = dup2(a.x); o[1] = dup2(a.y); o[2] = dup2(a.z); o[3] = dup2(a.w);
        o[4] = dup2(c.x); o[5] = dup2(c.y); o[6] = dup2(c.z); o[7] = 0ull;
    }

    const int r0 = tid * 4;
    const float* qg = g_q + ((size_t)bh * LL + r0) * DP;
    u64 q0[7], q1[7];
    {
        float4 a0 = *(const float4*)(qg + 0);
        float4 a1 = *(const float4*)(qg + 4);
        float4 b0 = *(const float4*)(qg + 8);
        float4 b1 = *(const float4*)(qg + 12);
        float4 c0 = *(const float4*)(qg + 16);
        float4 c1 = *(const float4*)(qg + 20);
        float4 d0 = *(const float4*)(qg + 24);
        float4 d1 = *(const float4*)(qg + 28);
        q0[0] = pk2(a0.x, b0.x); q0[1] = pk2(a0.y, b0.y); q0[2] = pk2(a0.z, b0.z);
        q0[3] = pk2(a0.w, b0.w); q0[4] = pk2(a1.x, b1.x); q0[5] = pk2(a1.y, b1.y);
        q0[6] = pk2(a1.z, b1.z);
        q1[0] = pk2(c0.x, d0.x); q1[1] = pk2(c0.y, d0.y); q1[2] = pk2(c0.z, d0.z);
        q1[3] = pk2(c0.w, d0.w); q1[4] = pk2(c1.x, d1.x); q1[5] = pk2(c1.y, d1.y);
        q1[6] = pk2(c1.z, d1.z);
    }
    __syncthreads();

    u64 acc0[7], acc1[7];
    u64 S0 = dup2(0.0f), S1 = dup2(0.0f);
#pragma unroll
    for (int j = 0; j < 7; ++j) { acc0[j] = S0; acc1[j] = S0; }

#pragma unroll 4
    for (int key = 0; key < KCH; ++key) {
        ulonglong2 ka = *(const ulonglong2*)(kd + key * 8);
        ulonglong2 kb = *(const ulonglong2*)(kd + key * 8 + 2);
        ulonglong2 kc = *(const ulonglong2*)(kd + key * 8 + 4);
        ulonglong2 ke = *(const ulonglong2*)(kd + key * 8 + 6);

        u64 s0 = mul2(q0[0], ka.x);
        u64 s1 = mul2(q1[0], ka.x);
        s0 = fma2(q0[1], ka.y, s0); s1 = fma2(q1[1], ka.y, s1);
        s0 = fma2(q0[2], kb.x, s0); s1 = fma2(q1[2], kb.x, s1);
        s0 = fma2(q0[3], kb.y, s0); s1 = fma2(q1[3], kb.y, s1);
        s0 = fma2(q0[4], kc.x, s0); s1 = fma2(q1[4], kc.x, s1);
        s0 = fma2(q0[5], kc.y, s0); s1 = fma2(q1[5], kc.y, s1);
        s0 = fma2(q0[6], ke.x, s0); s1 = fma2(q1[6], ke.x, s1);

        float e0, e1, e2, e3;
        up2(s0, e0, e1);
        up2(s1, e2, e3);
        u64 p0 = pk2(ex2f(e0), ex2f(e1));
        u64 p1 = pk2(ex2f(e2), ex2f(e3));
        S0 = add2(S0, p0);
        S1 = add2(S1, p1);

        ulonglong2 va = *(const ulonglong2*)(vd + key * 8);
        ulonglong2 vb = *(const ulonglong2*)(vd + key * 8 + 2);
        ulonglong2 vc = *(const ulonglong2*)(vd + key * 8 + 4);
        ulonglong2 ve = *(const ulonglong2*)(vd + key * 8 + 6);

        acc0[0] = fma2(p0, va.x, acc0[0]); acc1[0] = fma2(p1, va.x, acc1[0]);
        acc0[1] = fma2(p0, va.y, acc0[1]); acc1[1] = fma2(p1, va.y, acc1[1]);
        acc0[2] = fma2(p0, vb.x, acc0[2]); acc1[2] = fma2(p1, vb.x, acc1[2]);
        acc0[3] = fma2(p0, vb.y, acc0[3]); acc1[3] = fma2(p1, vb.y, acc1[3]);
        acc0[4] = fma2(p0, vc.x, acc0[4]); acc1[4] = fma2(p1, vc.x, acc1[4]);
        acc0[5] = fma2(p0, vc.y, acc0[5]); acc1[5] = fma2(p1, vc.y, acc1[5]);
        acc0[6] = fma2(p0, ve.x, acc0[6]); acc1[6] = fma2(p1, ve.x, acc1[6]);
    }

    float* pp = g_part + (((size_t)(ks * NB * HH + bh)) * LL + r0) * DP;
    float lo[7], hi[7], sl, sh;
#pragma unroll
    for (int j = 0; j < 7; ++j) up2(acc0[j], lo[j], hi[j]);
    up2(S0, sl, sh);
    ((float4*)pp)[0] = make_float4(lo[0], lo[1], lo[2], lo[3]);
    ((float4*)pp)[1] = make_float4(lo[4], lo[5], lo[6], sl);
    ((float4*)pp)[2] = make_float4(hi[0], hi[1], hi[2], hi[3]);
    ((float4*)pp)[3] = make_float4(hi[4], hi[5], hi[6], sh);
#pragma unroll
    for (int j = 0; j < 7; ++j) up2(acc1[j], lo[j], hi[j]);
    up2(S1, sl, sh);
    ((float4*)pp)[4] = make_float4(lo[0], lo[1], lo[2], lo[3]);
    ((float4*)pp)[5] = make_float4(lo[4], lo[5], lo[6], sl);
    ((float4*)pp)[6] = make_float4(hi[0], hi[1], hi[2], hi[3]);
    ((float4*)pp)[7] = make_float4(hi[4], hi[5], hi[6], sh);
}

// ---------------- Kernel 3: combine partials + normalize ----------------
__global__ void __launch_bounds__(256)
reduce_kernel(float* __restrict__ out)
{
    const int qi = blockIdx.x * 256 + threadIdx.x;   // 131072 queries
    const int bh = qi >> 10;
    const int l  = qi & 1023;

    float a0 = 0, a1 = 0, a2 = 0, a3 = 0, a4 = 0, a5 = 0, a6 = 0, S = 0;
#pragma unroll
    for (int ks = 0; ks < SPLIT; ++ks) {
        const float4* p = (const float4*)(g_part +
            (((size_t)(ks * NB * HH + bh)) * LL + l) * DP);
        float4 a = p[0], b = p[1];
        a0 += a.x; a1 += a.y; a2 += a.z; a3 += a.w;
        a4 += b.x; a5 += b.y; a6 += b.z; S  += b.w;
    }
    float inv = 1.0f / S;
    float* op = out + (size_t)qi * DDIM;
    op[0] = a0 * inv; op[1] = a1 * inv; op[2] = a2 * inv;
    op[3] = a3 * inv; op[4] = a4 * inv; op[5] = a5 * inv;
    op[6] = a6 * inv;
}

// ---------------- launch ----------------
extern "C" void kernel_launch(void* const* d_in, const int* in_sizes, int n_in,
                              void* d_out, int out_size)
{
    const float* x  = (const float*)d_in[0];
    const float* Wq = (const float*)d_in[1];
    const float* bq = (const float*)d_in[2];
    const float* Wk = (const float*)d_in[3];
    const float* bk = (const float*)d_in[4];
    const float* Wv = (const float*)d_in[5];
    const float* bv = (const float*)d_in[6];

    cudaFuncSetAttribute(qkv_gemm, cudaFuncAttributeMaxDynamicSharedMemorySize, GEMM_SMEM);
    cudaFuncSetAttribute(qkv_gemm, cudaFuncAttributePreferredSharedMemoryCarveout, 100);
    cudaFuncSetAttribute(attn_kernel, cudaFuncAttributePreferredSharedMemoryCarveout, 100);

    qkv_gemm<<<dim3(128, 3), 256, GEMM_SMEM>>>(x, Wq, bq, Wk, bk, Wv, bv);
    attn_kernel<<<NB * HH * SPLIT, 256>>>();
    reduce_kernel<<<NB * HH * LL / 256, 256>>>((float*)d_out);
}

// round 14
// speedup vs baseline: 1.1004x; 1.1004x over previous
#include <cuda_runtime.h>
#include <cstdint>

// Problem constants
#define NB   8
#define CIN  16
#define LL   1024
#define DDIM 7
#define SZ   112     // CIN*DDIM
#define HH   16
#define DP   8       // padded head dim
#define SPLIT 8
#define KCH  (LL / SPLIT)   // 128 keys per block

// Scratch: Q/K/V in [n][h][l][8] (4MB each), partials [ks][bh][l][8]
__device__ float g_q[NB * HH * LL * DP];   // q pre-scaled by log2(e)/32
__device__ float g_k[NB * HH * LL * DP];
__device__ float g_v[NB * HH * LL * DP];
__device__ float g_part[SPLIT * NB * HH * LL * DP];

// ---------------- f32x2 packed helpers ----------------
using u64 = unsigned long long;

__device__ __forceinline__ u64 pk2(float lo, float hi) {
    u64 r; asm("mov.b64 %0,{%1,%2};" : "=l"(r) : "f"(lo), "f"(hi)); return r;
}
__device__ __forceinline__ u64 dup2(float v) {
    u64 r; asm("mov.b64 %0,{%1,%1};" : "=l"(r) : "f"(v)); return r;
}
__device__ __forceinline__ void up2(u64 v, float& lo, float& hi) {
    asm("mov.b64 {%0,%1},%2;" : "=f"(lo), "=f"(hi) : "l"(v));
}
__device__ __forceinline__ u64 fma2(u64 a, u64 b, u64 c) {
    u64 d; asm("fma.rn.f32x2 %0,%1,%2,%3;" : "=l"(d) : "l"(a), "l"(b), "l"(c)); return d;
}
__device__ __forceinline__ u64 mul2(u64 a, u64 b) {
    u64 d; asm("mul.rn.f32x2 %0,%1,%2;" : "=l"(d) : "l"(a), "l"(b)); return d;
}
__device__ __forceinline__ u64 add2(u64 a, u64 b) {
    u64 d; asm("add.rn.f32x2 %0,%1,%2;" : "=l"(d) : "l"(a), "l"(b)); return d;
}
__device__ __forceinline__ float ex2f(float a) {
    float d; asm("ex2.approx.f32 %0,%1;" : "=f"(d) : "f"(a)); return d;
}
__device__ __forceinline__ unsigned tf32cvt(float v) {
    unsigned r; asm("cvt.rna.tf32.f32 %0,%1;" : "=r"(r) : "f"(v)); return r;
}

// ---------------- Kernel 1: QKV projection via tf32 mma.sync ----------------
// grid (128, 3): bx -> (n, l-tile of 64), by -> Wq/Wk/Wv. 256 threads = 8 warps.
// Mainloop identical to R13 (tensor pipe). NEW epilogue: accumulators staged
// through smem (stride-132 rows, <=2-way conflicts), then written to gmem as
// fully coalesced STG.128 runs — removes 28 scattered STG.32/thread.
#define SXT 72
#define SWS 116
#define OST 132                      // staging row stride (floats)
#define GEMM_SMEM ((SZ * SXT + SZ * SWS) * 4)

__global__ void __launch_bounds__(256, 2)
qkv_gemm(const float* __restrict__ x,
         const float* __restrict__ Wq, const float* __restrict__ bq,
         const float* __restrict__ Wk, const float* __restrict__ bk,
         const float* __restrict__ Wv, const float* __restrict__ bv)
{
    extern __shared__ unsigned smu[];
    unsigned* xs = smu;              // [112 f][72 l]  tf32 bits (reused as out-stage)
    unsigned* ws = smu + SZ * SXT;   // [112 c][116 f] tf32 bits
    float* os = (float*)smu;         // [64 l][132] staged output (32.8KB < xs area)

    const int tid = threadIdx.x;
    const int m = blockIdx.y;
    const float* W = (m == 0) ? Wq : ((m == 1) ? Wk : Wv);
    const float* b = (m == 0) ? bq : ((m == 1) ? bk : bv);
    float* og = (m == 0) ? g_q : ((m == 1) ? g_k : g_v);

    const int n  = blockIdx.x >> 4;          // 16 l-tiles per n
    const int l0 = (blockIdx.x & 15) << 6;

    // W -> ws[c][f] (tf32)
    for (int i = tid; i < SZ * SZ; i += 256)
        ws[(i / SZ) * SWS + (i % SZ)] = tf32cvt(W[i]);

    // x [c][l][dd] -> xs[f=c*7+dd][l] (tf32)
    const float* xb = x + ((size_t)n * CIN * LL + l0) * DDIM;
    for (int i = tid; i < CIN * 64 * DDIM; i += 256) {
        int c = i / (64 * DDIM);
        int r = i - c * (64 * DDIM);
        float v = xb[(size_t)c * LL * DDIM + r];
        int l = r / DDIM;
        int dd = r - l * DDIM;
        xs[(c * DDIM + dd) * SXT + l] = tf32cvt(v);
    }
    __syncthreads();

    const int wid  = tid >> 5;
    const int lane = tid & 31;
    const int gid  = lane >> 2;      // 0..7
    const int tig  = lane & 3;       // 0..3
    const int rt   = (wid & 3) * 16; // row tile within l-tile
    const int ch   = wid >> 2;       // col half
    const int cb   = ch * 56;        // base col

    float c0[7], c1[7], c2[7], c3[7];
#pragma unroll
    for (int nt = 0; nt < 7; ++nt) { c0[nt] = 0.f; c1[nt] = 0.f; c2[nt] = 0.f; c3[nt] = 0.f; }

#pragma unroll
    for (int k = 0; k < 14; ++k) {
        const int f0 = k * 8;
        unsigned a0 = xs[(f0 + tig) * SXT + rt + gid];
        unsigned a1 = xs[(f0 + tig) * SXT + rt + gid + 8];
        unsigned a2 = xs[(f0 + tig + 4) * SXT + rt + gid];
        unsigned a3 = xs[(f0 + tig + 4) * SXT + rt + gid + 8];
#pragma unroll
        for (int nt = 0; nt < 7; ++nt) {
            const int col = cb + nt * 8 + gid;
            unsigned b0 = ws[col * SWS + f0 + tig];
            unsigned b1 = ws[col * SWS + f0 + tig + 4];
            asm volatile(
                "mma.sync.aligned.m16n8k8.row.col.f32.tf32.tf32.f32 "
                "{%0,%1,%2,%3}, {%4,%5,%6,%7}, {%8,%9}, {%0,%1,%2,%3};"
                : "+f"(c0[nt]), "+f"(c1[nt]), "+f"(c2[nt]), "+f"(c3[nt])
                : "r"(a0), "r"(a1), "r"(a2), "r"(a3), "r"(b0), "r"(b1));
        }
    }
    __syncthreads();   // xs no longer needed; reuse as output staging

    // Zero pad columns (slot = h*8+7) so final copy can be unconditional.
    for (int i = tid; i < 64 * HH; i += 256)
        os[(i >> 4) * OST + (i & 15) * 8 + 7] = 0.0f;
    __syncthreads();

    // Stage accumulators: os[l][slot], slot = col + col/7 (maps (h,d)->h*8+d).
    const float SC = (m == 0) ? 0.04508422002778011f : 1.0f;
    const int rowA = rt + gid;
    const int rowB = rowA + 8;
#pragma unroll
    for (int nt = 0; nt < 7; ++nt) {
        const int colA = cb + nt * 8 + 2 * tig;
        const int colB = colA + 1;
        const float bA = __ldg(&b[colA]);
        const float bB = __ldg(&b[colB]);
        const int slA = colA + colA / 7;
        const int slB = colB + colB / 7;
        os[rowA * OST + slA] = (c0[nt] + bA) * SC;
        os[rowA * OST + slB] = (c1[nt] + bB) * SC;
        os[rowB * OST + slA] = (c2[nt] + bA) * SC;
        os[rowB * OST + slB] = (c3[nt] + bB) * SC;
    }
    __syncthreads();

    // Coalesced write-out: per head h, 64 rows x 8 floats contiguous in og.
    // i -> (h, l, half): dst runs are consecutive float4 within each h-block.
    float* ob = og + (((size_t)n * HH) * LL + l0) * DP;
    for (int i = tid; i < HH * 64 * 2; i += 256) {
        const int h    = i >> 7;
        const int rem  = i & 127;
        const int l    = rem >> 1;
        const int half = rem & 1;
        float4 v = *(const float4*)&os[l * OST + h * 8 + half * 4];
        *(float4*)&ob[((size_t)h * LL + l) * DP + half * 4] = v;
    }
}

// ---------------- Kernel 2: key-split attention partials (R10 exact) ----------------
__global__ void __launch_bounds__(256, 2)
attn_kernel()
{
    __shared__ u64 kd[KCH * 8];
    __shared__ u64 vd[KCH * 8];

    const int tid = threadIdx.x;
    const int bh  = blockIdx.x >> 3;
    const int ks  = blockIdx.x & 7;
    const int kbase = ks * KCH;

    if (tid < KCH) {
        const float4* kp = (const float4*)(g_k + ((size_t)bh * LL + kbase + tid) * DP);
        float4 a = kp[0], c = kp[1];
        u64* o = kd + tid * 8;
        o[0] = dup2(a.x); o[1] = dup2(a.y); o[2] = dup2(a.z); o[3] = dup2(a.w);
        o[4] = dup2(c.x); o[5] = dup2(c.y); o[6] = dup2(c.z); o[7] = 0ull;
    } else {
        int t = tid - KCH;
        const float4* vp = (const float4*)(g_v + ((size_t)bh * LL + kbase + t) * DP);
        float4 a = vp[0], c = vp[1];
        u64* o = vd + t * 8;
        o[0] = dup2(a.x); o[1] = dup2(a.y); o[2] = dup2(a.z); o[3] = dup2(a.w);
        o[4] = dup2(c.x); o[5] = dup2(c.y); o[6] = dup2(c.z); o[7] = 0ull;
    }

    const int r0 = tid * 4;
    const float* qg = g_q + ((size_t)bh * LL + r0) * DP;
    u64 q0[7], q1[7];
    {
        float4 a0 = *(const float4*)(qg + 0);
        float4 a1 = *(const float4*)(qg + 4);
        float4 b0 = *(const float4*)(qg + 8);
        float4 b1 = *(const float4*)(qg + 12);
        float4 c0 = *(const float4*)(qg + 16);
        float4 c1 = *(const float4*)(qg + 20);
        float4 d0 = *(const float4*)(qg + 24);
        float4 d1 = *(const float4*)(qg + 28);
        q0[0] = pk2(a0.x, b0.x); q0[1] = pk2(a0.y, b0.y); q0[2] = pk2(a0.z, b0.z);
        q0[3] = pk2(a0.w, b0.w); q0[4] = pk2(a1.x, b1.x); q0[5] = pk2(a1.y, b1.y);
        q0[6] = pk2(a1.z, b1.z);
        q1[0] = pk2(c0.x, d0.x); q1[1] = pk2(c0.y, d0.y); q1[2] = pk2(c0.z, d0.z);
        q1[3] = pk2(c0.w, d0.w); q1[4] = pk2(c1.x, d1.x); q1[5] = pk2(c1.y, d1.y);
        q1[6] = pk2(c1.z, d1.z);
    }
    __syncthreads();

    u64 acc0[7], acc1[7];
    u64 S0 = dup2(0.0f), S1 = dup2(0.0f);
#pragma unroll
    for (int j = 0; j < 7; ++j) { acc0[j] = S0; acc1[j] = S0; }

#pragma unroll 4
    for (int key = 0; key < KCH; ++key) {
        ulonglong2 ka = *(const ulonglong2*)(kd + key * 8);
        ulonglong2 kb = *(const ulonglong2*)(kd + key * 8 + 2);
        ulonglong2 kc = *(const ulonglong2*)(kd + key * 8 + 4);
        ulonglong2 ke = *(const ulonglong2*)(kd + key * 8 + 6);

        u64 s0 = mul2(q0[0], ka.x);
        u64 s1 = mul2(q1[0], ka.x);
        s0 = fma2(q0[1], ka.y, s0); s1 = fma2(q1[1], ka.y, s1);
        s0 = fma2(q0[2], kb.x, s0); s1 = fma2(q1[2], kb.x, s1);
        s0 = fma2(q0[3], kb.y, s0); s1 = fma2(q1[3], kb.y, s1);
        s0 = fma2(q0[4], kc.x, s0); s1 = fma2(q1[4], kc.x, s1);
        s0 = fma2(q0[5], kc.y, s0); s1 = fma2(q1[5], kc.y, s1);
        s0 = fma2(q0[6], ke.x, s0); s1 = fma2(q1[6], ke.x, s1);

        float e0, e1, e2, e3;
        up2(s0, e0, e1);
        up2(s1, e2, e3);
        u64 p0 = pk2(ex2f(e0), ex2f(e1));
        u64 p1 = pk2(ex2f(e2), ex2f(e3));
        S0 = add2(S0, p0);
        S1 = add2(S1, p1);

        ulonglong2 va = *(const ulonglong2*)(vd + key * 8);
        ulonglong2 vb = *(const ulonglong2*)(vd + key * 8 + 2);
        ulonglong2 vc = *(const ulonglong2*)(vd + key * 8 + 4);
        ulonglong2 ve = *(const ulonglong2*)(vd + key * 8 + 6);

        acc0[0] = fma2(p0, va.x, acc0[0]); acc1[0] = fma2(p1, va.x, acc1[0]);
        acc0[1] = fma2(p0, va.y, acc0[1]); acc1[1] = fma2(p1, va.y, acc1[1]);
        acc0[2] = fma2(p0, vb.x, acc0[2]); acc1[2] = fma2(p1, vb.x, acc1[2]);
        acc0[3] = fma2(p0, vb.y, acc0[3]); acc1[3] = fma2(p1, vb.y, acc1[3]);
        acc0[4] = fma2(p0, vc.x, acc0[4]); acc1[4] = fma2(p1, vc.x, acc1[4]);
        acc0[5] = fma2(p0, vc.y, acc0[5]); acc1[5] = fma2(p1, vc.y, acc1[5]);
        acc0[6] = fma2(p0, ve.x, acc0[6]); acc1[6] = fma2(p1, ve.x, acc1[6]);
    }

    float* pp = g_part + (((size_t)(ks * NB * HH + bh)) * LL + r0) * DP;
    float lo[7], hi[7], sl, sh;
#pragma unroll
    for (int j = 0; j < 7; ++j) up2(acc0[j], lo[j], hi[j]);
    up2(S0, sl, sh);
    ((float4*)pp)[0] = make_float4(lo[0], lo[1], lo[2], lo[3]);
    ((float4*)pp)[1] = make_float4(lo[4], lo[5], lo[6], sl);
    ((float4*)pp)[2] = make_float4(hi[0], hi[1], hi[2], hi[3]);
    ((float4*)pp)[3] = make_float4(hi[4], hi[5], hi[6], sh);
#pragma unroll
    for (int j = 0; j < 7; ++j) up2(acc1[j], lo[j], hi[j]);
    up2(S1, sl, sh);
    ((float4*)pp)[4] = make_float4(lo[0], lo[1], lo[2], lo[3]);
    ((float4*)pp)[5] = make_float4(lo[4], lo[5], lo[6], sl);
    ((float4*)pp)[6] = make_float4(hi[0], hi[1], hi[2], hi[3]);
    ((float4*)pp)[7] = make_float4(hi[4], hi[5], hi[6], sh);
}

// ---------------- Kernel 3: combine partials + normalize ----------------
__global__ void __launch_bounds__(256)
reduce_kernel(float* __restrict__ out)
{
    const int qi = blockIdx.x * 256 + threadIdx.x;   // 131072 queries
    const int bh = qi >> 10;
    const int l  = qi & 1023;

    float a0 = 0, a1 = 0, a2 = 0, a3 = 0, a4 = 0, a5 = 0, a6 = 0, S = 0;
#pragma unroll
    for (int ks = 0; ks < SPLIT; ++ks) {
        const float4* p = (const float4*)(g_part +
            (((size_t)(ks * NB * HH + bh)) * LL + l) * DP);
        float4 a = p[0], b = p[1];
        a0 += a.x; a1 += a.y; a2 += a.z; a3 += a.w;
        a4 += b.x; a5 += b.y; a6 += b.z; S  += b.w;
    }
    float inv = 1.0f / S;
    float* op = out + (size_t)qi * DDIM;
    op[0] = a0 * inv; op[1] = a1 * inv; op[2] = a2 * inv;
    op[3] = a3 * inv; op[4] = a4 * inv; op[5] = a5 * inv;
    op[6] = a6 * inv;
}

// ---------------- launch ----------------
extern "C" void kernel_launch(void* const* d_in, const int* in_sizes, int n_in,
                              void* d_out, int out_size)
{
    const float* x  = (const float*)d_in[0];
    const float* Wq = (const float*)d_in[1];
    const float* bq = (const float*)d_in[2];
    const float* Wk = (const float*)d_in[3];
    const float* bk = (const float*)d_in[4];
    const float* Wv = (const float*)d_in[5];
    const float* bv = (const float*)d_in[6];

    cudaFuncSetAttribute(qkv_gemm, cudaFuncAttributeMaxDynamicSharedMemorySize, GEMM_SMEM);
    cudaFuncSetAttribute(qkv_gemm, cudaFuncAttributePreferredSharedMemoryCarveout, 100);
    cudaFuncSetAttribute(attn_kernel, cudaFuncAttributePreferredSharedMemoryCarveout, 100);

    qkv_gemm<<<dim3(128, 3), 256, GEMM_SMEM>>>(x, Wq, bq, Wk, bk, Wv, bv);
    attn_kernel<<<NB * HH * SPLIT, 256>>>();
    reduce_kernel<<<NB * HH * LL / 256, 256>>>((float*)d_out);
}

// round 16
// speedup vs baseline: 1.3675x; 1.2427x over previous
#include <cuda_runtime.h>
#include <cstdint>

// Problem constants
#define NB   8
#define CIN  16
#define LL   1024
#define DDIM 7
#define SZ   112     // CIN*DDIM
#define HH   16
#define DP   8       // padded head dim
#define SPLIT 8
#define KCH  (LL / SPLIT)   // 128 keys per block

// Scratch: Q/K/V in [n][h][l][8] (4MB each), partials [ks][bh][l][8]
__device__ float g_q[NB * HH * LL * DP];   // q pre-scaled by log2(e)/32
__device__ float g_k[NB * HH * LL * DP];
__device__ float g_v[NB * HH * LL * DP];
__device__ float g_part[SPLIT * NB * HH * LL * DP];

__device__ __forceinline__ float ex2f(float a) {
    float d; asm("ex2.approx.f32 %0,%1;" : "=f"(d) : "f"(a)); return d;
}
__device__ __forceinline__ unsigned tf32cvt(float v) {
    unsigned r; asm("cvt.rna.tf32.f32 %0,%1;" : "=r"(r) : "f"(v)); return r;
}
#define MMA_TF32(c0,c1,c2,c3,a0,a1,a2,a3,b0,b1) \
    asm volatile( \
        "mma.sync.aligned.m16n8k8.row.col.f32.tf32.tf32.f32 " \
        "{%0,%1,%2,%3}, {%4,%5,%6,%7}, {%8,%9}, {%0,%1,%2,%3};" \
        : "+f"(c0), "+f"(c1), "+f"(c2), "+f"(c3) \
        : "r"(a0), "r"(a1), "r"(a2), "r"(a3), "r"(b0), "r"(b1))

// ---------------- Kernel 1: QKV projection via tf32 mma.sync (R14 best) ----------------
#define SXT 72
#define SWS 116
#define OST 132
#define GEMM_SMEM ((SZ * SXT + SZ * SWS) * 4)

__global__ void __launch_bounds__(256, 2)
qkv_gemm(const float* __restrict__ x,
         const float* __restrict__ Wq, const float* __restrict__ bq,
         const float* __restrict__ Wk, const float* __restrict__ bk,
         const float* __restrict__ Wv, const float* __restrict__ bv)
{
    extern __shared__ unsigned smu[];
    unsigned* xs = smu;              // [112 f][72 l]  tf32 bits (reused as out-stage)
    unsigned* ws = smu + SZ * SXT;   // [112 c][116 f] tf32 bits
    float* os = (float*)smu;         // [64 l][132] staged output

    const int tid = threadIdx.x;
    const int m = blockIdx.y;
    const float* W = (m == 0) ? Wq : ((m == 1) ? Wk : Wv);
    const float* b = (m == 0) ? bq : ((m == 1) ? bk : bv);
    float* og = (m == 0) ? g_q : ((m == 1) ? g_k : g_v);

    const int n  = blockIdx.x >> 4;
    const int l0 = (blockIdx.x & 15) << 6;

    for (int i = tid; i < SZ * SZ; i += 256)
        ws[(i / SZ) * SWS + (i % SZ)] = tf32cvt(W[i]);

    const float* xb = x + ((size_t)n * CIN * LL + l0) * DDIM;
    for (int i = tid; i < CIN * 64 * DDIM; i += 256) {
        int c = i / (64 * DDIM);
        int r = i - c * (64 * DDIM);
        float v = xb[(size_t)c * LL * DDIM + r];
        int l = r / DDIM;
        int dd = r - l * DDIM;
        xs[(c * DDIM + dd) * SXT + l] = tf32cvt(v);
    }
    __syncthreads();

    const int wid  = tid >> 5;
    const int lane = tid & 31;
    const int gid  = lane >> 2;
    const int tig  = lane & 3;
    const int rt   = (wid & 3) * 16;
    const int ch   = wid >> 2;
    const int cb   = ch * 56;

    float c0[7], c1[7], c2[7], c3[7];
#pragma unroll
    for (int nt = 0; nt < 7; ++nt) { c0[nt] = 0.f; c1[nt] = 0.f; c2[nt] = 0.f; c3[nt] = 0.f; }

#pragma unroll
    for (int k = 0; k < 14; ++k) {
        const int f0 = k * 8;
        unsigned a0 = xs[(f0 + tig) * SXT + rt + gid];
        unsigned a1 = xs[(f0 + tig) * SXT + rt + gid + 8];
        unsigned a2 = xs[(f0 + tig + 4) * SXT + rt + gid];
        unsigned a3 = xs[(f0 + tig + 4) * SXT + rt + gid + 8];
#pragma unroll
        for (int nt = 0; nt < 7; ++nt) {
            const int col = cb + nt * 8 + gid;
            unsigned b0 = ws[col * SWS + f0 + tig];
            unsigned b1 = ws[col * SWS + f0 + tig + 4];
            MMA_TF32(c0[nt], c1[nt], c2[nt], c3[nt], a0, a1, a2, a3, b0, b1);
        }
    }
    __syncthreads();

    for (int i = tid; i < 64 * HH; i += 256)
        os[(i >> 4) * OST + (i & 15) * 8 + 7] = 0.0f;
    __syncthreads();

    const float SC = (m == 0) ? 0.04508422002778011f : 1.0f;
    const int rowA = rt + gid;
    const int rowB = rowA + 8;
#pragma unroll
    for (int nt = 0; nt < 7; ++nt) {
        const int colA = cb + nt * 8 + 2 * tig;
        const int colB = colA + 1;
        const float bA = __ldg(&b[colA]);
        const float bB = __ldg(&b[colB]);
        const int slA = colA + colA / 7;
        const int slB = colB + colB / 7;
        os[rowA * OST + slA] = (c0[nt] + bA) * SC;
        os[rowA * OST + slB] = (c1[nt] + bB) * SC;
        os[rowB * OST + slA] = (c2[nt] + bA) * SC;
        os[rowB * OST + slB] = (c3[nt] + bB) * SC;
    }
    __syncthreads();

    float* ob = og + (((size_t)n * HH) * LL + l0) * DP;
    for (int i = tid; i < HH * 64 * 2; i += 256) {
        const int h    = i >> 7;
        const int rem  = i & 127;
        const int l    = rem >> 1;
        const int half = rem & 1;
        float4 v = *(const float4*)&os[l * OST + h * 8 + half * 4];
        *(float4*)&ob[((size_t)h * LL + l) * DP + half * 4] = v;
    }
}

// ---------------- Kernel 2: tensor-core key-split attention ----------------
// grid 1024 = (bh, ks of 128 keys), 256 threads = 8 warps.
// Warp w: 128 queries (8 row-tiles of 16). Per row-tile:
//   16x QK mma (tf32) -> ex2 on C-frags -> cvt -> stage P in per-warp smem
//   -> 16x PV mma with ones-column V (col7 = 1.0 gives softmax sum for free).
// Banks: kt stride 12 / vt stride 24 -> frag loads cover 32 banks disjointly;
// P reload (gid*4+tig) conflict-free.
#define KTS 12
#define VTS 24
#define PST 132
#define ATT_SMEM ((KCH * KTS + KCH * VTS + 8 * 16 * PST) * 4)

__global__ void __launch_bounds__(256)
attn_kernel()
{
    extern __shared__ unsigned asmem[];
    unsigned* kt = asmem;                        // [128 key][12]  tf32 K
    unsigned* vt = asmem + KCH * KTS;            // [128 key][24]  tf32 V (+ones)
    unsigned* ps = asmem + KCH * (KTS + VTS);    // [8 warp][16 q][132]  tf32 P

    const int tid = threadIdx.x;
    const int bh  = blockIdx.x >> 3;
    const int ks  = blockIdx.x & 7;
    const int kbase = ks * KCH;

    // Fill K/V tiles (tf32). g_k/g_v slot 7: K pad stays 0, V pad becomes 1.0.
    const float* kg = g_k + ((size_t)bh * LL + kbase) * DP;
    const float* vg = g_v + ((size_t)bh * LL + kbase) * DP;
    for (int i = tid; i < KCH * DP; i += 256) {
        int key = i >> 3, d = i & 7;
        kt[key * KTS + d] = tf32cvt(kg[i]);
        vt[key * VTS + d] = tf32cvt((d == 7) ? 1.0f : vg[i]);
    }
    __syncthreads();

    const int wid  = tid >> 5;
    const int lane = tid & 31;
    const int gid  = lane >> 2;      // 0..7
    const int tig  = lane & 3;       // 0..3
    unsigned* pw = ps + wid * 16 * PST;
    const float* qb = g_q + ((size_t)bh * LL + wid * 128) * DP;

#pragma unroll 1
    for (int t = 0; t < 8; ++t) {
        const float* qr = qb + t * 16 * DP;
        // Q A-frags straight from gmem (L2-resident; reused by 8 ks-blocks)
        unsigned a0 = tf32cvt(qr[gid * DP + tig]);
        unsigned a1 = tf32cvt(qr[(gid + 8) * DP + tig]);
        unsigned a2 = tf32cvt(qr[gid * DP + tig + 4]);
        unsigned a3 = tf32cvt(qr[(gid + 8) * DP + tig + 4]);

        // Scores + exp + stage P
#pragma unroll
        for (int g = 0; g < 16; ++g) {
            unsigned b0 = kt[(g * 8 + gid) * KTS + tig];
            unsigned b1 = kt[(g * 8 + gid) * KTS + tig + 4];
            float s0 = 0.f, s1 = 0.f, s2 = 0.f, s3 = 0.f;
            MMA_TF32(s0, s1, s2, s3, a0, a1, a2, a3, b0, b1);
            uint2 lo = make_uint2(tf32cvt(ex2f(s0)), tf32cvt(ex2f(s1)));
            uint2 hi = make_uint2(tf32cvt(ex2f(s2)), tf32cvt(ex2f(s3)));
            *(uint2*)&pw[gid * PST + g * 8 + 2 * tig] = lo;
            *(uint2*)&pw[(gid + 8) * PST + g * 8 + 2 * tig] = hi;
        }
        __syncwarp();

        // P x V (+ones col): 16 K-steps of 8 keys
        float o0 = 0.f, o1 = 0.f, o2 = 0.f, o3 = 0.f;
#pragma unroll
        for (int s = 0; s < 16; ++s) {
            unsigned pa0 = pw[gid * PST + s * 8 + tig];
            unsigned pa1 = pw[(gid + 8) * PST + s * 8 + tig];
            unsigned pa2 = pw[gid * PST + s * 8 + tig + 4];
            unsigned pa3 = pw[(gid + 8) * PST + s * 8 + tig + 4];
            unsigned b0 = vt[(s * 8 + tig) * VTS + gid];
            unsigned b1 = vt[(s * 8 + tig + 4) * VTS + gid];
            MMA_TF32(o0, o1, o2, o3, pa0, pa1, pa2, pa3, b0, b1);
        }
        __syncwarp();

        // Write partials [ks][bh][l][8]: dims 2tig,2tig+1 (col 7 = sum S)
        const int q0r = wid * 128 + t * 16 + gid;
        float* pp = g_part + (((size_t)(ks * NB * HH + bh)) * LL + q0r) * DP;
        *(float2*)&pp[2 * tig] = make_float2(o0, o1);
        *(float2*)&pp[8 * DP + 2 * tig] = make_float2(o2, o3);
    }
}

// ---------------- Kernel 3: combine partials + normalize ----------------
__global__ void __launch_bounds__(256)
reduce_kernel(float* __restrict__ out)
{
    const int qi = blockIdx.x * 256 + threadIdx.x;   // 131072 queries
    const int bh = qi >> 10;
    const int l  = qi & 1023;

    float a0 = 0, a1 = 0, a2 = 0, a3 = 0, a4 = 0, a5 = 0, a6 = 0, S = 0;
#pragma unroll
    for (int ks = 0; ks < SPLIT; ++ks) {
        const float4* p = (const float4*)(g_part +
            (((size_t)(ks * NB * HH + bh)) * LL + l) * DP);
        float4 a = p[0], b = p[1];
        a0 += a.x; a1 += a.y; a2 += a.z; a3 += a.w;
        a4 += b.x; a5 += b.y; a6 += b.z; S  += b.w;
    }
    float inv = 1.0f / S;
    float* op = out + (size_t)qi * DDIM;
    op[0] = a0 * inv; op[1] = a1 * inv; op[2] = a2 * inv;
    op[3] = a3 * inv; op[4] = a4 * inv; op[5] = a5 * inv;
    op[6] = a6 * inv;
}

// ---------------- launch ----------------
extern "C" void kernel_launch(void* const* d_in, const int* in_sizes, int n_in,
                              void* d_out, int out_size)
{
    const float* x  = (const float*)d_in[0];
    const float* Wq = (const float*)d_in[1];
    const float* bq = (const float*)d_in[2];
    const float* Wk = (const float*)d_in[3];
    const float* bk = (const float*)d_in[4];
    const float* Wv = (const float*)d_in[5];
    const float* bv = (const float*)d_in[6];

    cudaFuncSetAttribute(qkv_gemm, cudaFuncAttributeMaxDynamicSharedMemorySize, GEMM_SMEM);
    cudaFuncSetAttribute(attn_kernel, cudaFuncAttributeMaxDynamicSharedMemorySize, ATT_SMEM);
    cudaFuncSetAttribute(qkv_gemm, cudaFuncAttributePreferredSharedMemoryCarveout, 100);
    cudaFuncSetAttribute(attn_kernel, cudaFuncAttributePreferredSharedMemoryCarveout, 100);

    qkv_gemm<<<dim3(128, 3), 256, GEMM_SMEM>>>(x, Wq, bq, Wk, bk, Wv, bv);
    attn_kernel<<<NB * HH * SPLIT, 256, ATT_SMEM>>>();
    reduce_kernel<<<NB * HH * LL / 256, 256>>>((float*)d_out);
}